// round 3
// baseline (speedup 1.0000x reference)
#include <cuda_runtime.h>
#include <cuda_bf16.h>
#include <cstdint>
#include <cstddef>

// ---------------------------------------------------------------------------
// Problem constants
// ---------------------------------------------------------------------------
#define BATCH   256
#define NPTS    1024
#define HID     256
#define ACT     6

// device scratch (static globals: allowed, no allocation)
__device__ float g_feat[BATCH * 512];    // pooled PointNet feature
__device__ float g_gruh[BATCH * HID];    // initial GRU hidden state
__device__ float g_WhhT[HID * 768];      // W_hh transposed to [k][j]

// ---------------------------------------------------------------------------
// zero the feature accumulator (maxpool identity = 0 since post-relu >= 0)
// ---------------------------------------------------------------------------
__global__ void zero_feat_kernel() {
    int i = blockIdx.x * 256 + threadIdx.x;   // grid 512 x 256 = 131072
    g_feat[i] = 0.f;
}

// ---------------------------------------------------------------------------
// transpose W_hh [768,256] -> g_WhhT [256,768] (coalesced GEMM loads later)
// ---------------------------------------------------------------------------
__global__ void transpose_whh_kernel(const float* __restrict__ Whh) {
    int idx = blockIdx.x * 256 + threadIdx.x;   // 768 blocks -> 196608
    int k = idx / 768;
    int j = idx - k * 768;
    g_WhhT[idx] = Whh[j * 256 + k];
}

// ---------------------------------------------------------------------------
// Fused PointNet encoder: per-point 3->64->128->512 MLP + maxpool
// grid (8 chunks, 256 batches), 256 threads, 1 block handles 128 points
// ---------------------------------------------------------------------------
#define ENC_RB_LD 132   // padded row length for H128T tile (16B-aligned)
#define ENC_SMEM_FLOATS (16384 + 128*ENC_RB_LD + 2048)

__global__ void __launch_bounds__(256) enc_kernel(
    const float* __restrict__ data,
    const float* __restrict__ w1, const float* __restrict__ b1,
    const float* __restrict__ w2, const float* __restrict__ b2,
    const float* __restrict__ w3, const float* __restrict__ b3)
{
    extern __shared__ float sm[];
    float* rA   = sm;                       // 16384: H64T[64][128] + W2[64][128]; then W3 tile [128][128]
    float* rB   = sm + 16384;               // 128 * ENC_RB_LD : H128T[j][i]
    float* sRed = rB + 128 * ENC_RB_LD;     // 16*128 column-max partials
    __shared__ float sPts[128 * 3];

    const int tid   = threadIdx.x;
    const int b     = blockIdx.y;
    const int chunk = blockIdx.x;

    // ---- load 128 points + stage W2 in smem ----
    const float* dptr = data + (size_t)(b * NPTS + chunk * 128) * 3;
    for (int i = tid; i < 384; i += 256) sPts[i] = dptr[i];
    for (int i = tid * 4; i < 8192; i += 1024)
        *(float4*)(rA + 8192 + i) = *(const float4*)(w2 + i);
    __syncthreads();

    // ---- layer 1: H64T[k][i] = relu(p . w1col + b1) ----
    #pragma unroll
    for (int it = 0; it < 32; ++it) {
        int idx = tid + it * 256;
        int k = idx >> 7, i = idx & 127;
        float p0 = sPts[i*3], p1 = sPts[i*3+1], p2 = sPts[i*3+2];
        float v = b1[k] + p0 * w1[k] + p1 * w1[64 + k] + p2 * w1[128 + k];
        rA[idx] = fmaxf(v, 0.f);
    }
    __syncthreads();

    const int ty = tid >> 4, tx = tid & 15;
    const int i0 = ty * 8, j0 = tx * 8;

    // ---- layer 2: C[i][j] = relu(H64T^T @ W2 + b2) -> rB as H128T[j][i] ----
    {
        float acc[8][8];
        #pragma unroll
        for (int a = 0; a < 8; ++a)
            #pragma unroll
            for (int c = 0; c < 8; ++c) acc[a][c] = 0.f;

        #pragma unroll 4
        for (int k = 0; k < 64; ++k) {
            float av[8], wv[8];
            *(float4*)&av[0] = *(float4*)(rA + k*128 + i0);
            *(float4*)&av[4] = *(float4*)(rA + k*128 + i0 + 4);
            *(float4*)&wv[0] = *(float4*)(rA + 8192 + k*128 + j0);
            *(float4*)&wv[4] = *(float4*)(rA + 8192 + k*128 + j0 + 4);
            #pragma unroll
            for (int a = 0; a < 8; ++a)
                #pragma unroll
                for (int c = 0; c < 8; ++c) acc[a][c] += av[a] * wv[c];
        }
        float bj[8];
        #pragma unroll
        for (int c = 0; c < 8; ++c) bj[c] = b2[j0 + c];
        #pragma unroll
        for (int c = 0; c < 8; ++c)
            #pragma unroll
            for (int a = 0; a < 8; ++a)
                rB[(j0 + c) * ENC_RB_LD + i0 + a] = fmaxf(acc[a][c] + bj[c], 0.f);
    }
    __syncthreads();

    // ---- layer 3 (4 chunks of 128 cols) + column max + global atomicMax ----
    for (int nc = 0; nc < 4; ++nc) {
        for (int i4 = tid * 4; i4 < 16384; i4 += 1024) {
            int k = i4 >> 7, j = i4 & 127;
            *(float4*)(rA + i4) = *(const float4*)(w3 + (size_t)k * 512 + nc * 128 + j);
        }
        __syncthreads();

        float acc[8][8];
        #pragma unroll
        for (int a = 0; a < 8; ++a)
            #pragma unroll
            for (int c = 0; c < 8; ++c) acc[a][c] = 0.f;

        #pragma unroll 2
        for (int k = 0; k < 128; ++k) {
            float av[8], wv[8];
            *(float4*)&av[0] = *(float4*)(rB + k*ENC_RB_LD + i0);
            *(float4*)&av[4] = *(float4*)(rB + k*ENC_RB_LD + i0 + 4);
            *(float4*)&wv[0] = *(float4*)(rA + k*128 + j0);
            *(float4*)&wv[4] = *(float4*)(rA + k*128 + j0 + 4);
            #pragma unroll
            for (int a = 0; a < 8; ++a)
                #pragma unroll
                for (int c = 0; c < 8; ++c) acc[a][c] += av[a] * wv[c];
        }
        #pragma unroll
        for (int c = 0; c < 8; ++c) {
            float bv = b3[nc * 128 + j0 + c];
            float m = 0.f;
            #pragma unroll
            for (int a = 0; a < 8; ++a)
                m = fmaxf(m, fmaxf(acc[a][c] + bv, 0.f));
            sRed[ty * 128 + j0 + c] = m;
        }
        __syncthreads();
        if (tid < 128) {
            float m = sRed[tid];
            #pragma unroll
            for (int r = 1; r < 16; ++r) m = fmaxf(m, sRed[r * 128 + tid]);
            atomicMax((int*)&g_feat[b * 512 + nc * 128 + tid], __float_as_int(m));
        }
        __syncthreads();
    }
}

// ---------------------------------------------------------------------------
// Head MLP: 512 -> 256 -> 128 -> 256 (per batch row)
// ---------------------------------------------------------------------------
__global__ void __launch_bounds__(256) head_kernel(
    const float* __restrict__ w1, const float* __restrict__ b1,
    const float* __restrict__ w2, const float* __restrict__ b2,
    const float* __restrict__ w3, const float* __restrict__ b3)
{
    __shared__ float sh[512];
    __shared__ float s1[256];
    __shared__ float s2[128];
    int b = blockIdx.x, tid = threadIdx.x;
    sh[tid]       = g_feat[b * 512 + tid];
    sh[tid + 256] = g_feat[b * 512 + 256 + tid];
    __syncthreads();
    {
        float a = b1[tid];
        #pragma unroll 4
        for (int k = 0; k < 512; ++k) a += sh[k] * w1[(size_t)k * 256 + tid];
        s1[tid] = fmaxf(a, 0.f);
    }
    __syncthreads();
    if (tid < 128) {
        float a = b2[tid];
        #pragma unroll 4
        for (int k = 0; k < 256; ++k) a += s1[k] * w2[k * 128 + tid];
        s2[tid] = fmaxf(a, 0.f);
    }
    __syncthreads();
    {
        float a = b3[tid];
        #pragma unroll 4
        for (int k = 0; k < 128; ++k) a += s2[k] * w3[k * 256 + tid];
        g_gruh[b * HID + tid] = a;
    }
}

// ---------------------------------------------------------------------------
// GRU rollout: 86 blocks x 3 batch rows, 384 threads, full 50-step loop
// in-kernel (batch rows are independent -> no grid sync needed)
// ---------------------------------------------------------------------------
#define GRU_SMEM_FLOATS (4608 + 768 + 768 + 16384 + 4096 + 384 + 64 + 64 + 8 + 768 + 24 + 2304 + 2304 + 192 + 192)

__device__ __forceinline__ float sigf(float x) { return 1.f / (1.f + __expf(-x)); }
__device__ __forceinline__ float tanhfast(float x) { return 2.f / (1.f + __expf(-2.f * x)) - 1.f; }

__global__ void __launch_bounds__(384) gru_kernel(
    const float* __restrict__ Wih, const float* __restrict__ bih, const float* __restrict__ bhh,
    const float* __restrict__ ow1, const float* __restrict__ ob1,
    const float* __restrict__ ow2, const float* __restrict__ ob2,
    const float* __restrict__ ow3, const float* __restrict__ ob3,
    const int* __restrict__ horizon_p, float* __restrict__ out, int out_size)
{
    extern __shared__ float sm[];
    float* s_Wih = sm;                  // 768*6
    float* s_bih = s_Wih + 4608;        // 768
    float* s_bhh = s_bih + 768;         // 768
    float* s_w1  = s_bhh + 768;         // 256*64
    float* s_w2  = s_w1 + 16384;        // 64*64
    float* s_w3  = s_w2 + 4096;         // 64*6
    float* s_b1  = s_w3 + 384;          // 64
    float* s_b2  = s_b1 + 64;           // 64
    float* s_b3  = s_b2 + 64;           // 8
    float* s_h   = s_b3 + 8;            // 3*256
    float* s_x   = s_h + 768;           // 3*8
    float* s_gh  = s_x + 24;            // 3*768
    float* s_pt  = s_gh + 2304;         // 3*768
    float* s_o1  = s_pt + 2304;         // 3*64
    float* s_o2  = s_o1 + 192;          // 3*64

    const int tid = threadIdx.x;
    const int b0  = blockIdx.x * 3;

    for (int i = tid; i < 4608;  i += 384) s_Wih[i] = Wih[i];
    for (int i = tid; i < 768;   i += 384) { s_bih[i] = bih[i]; s_bhh[i] = bhh[i]; }
    for (int i = tid; i < 16384; i += 384) s_w1[i] = ow1[i];
    for (int i = tid; i < 4096;  i += 384) s_w2[i] = ow2[i];
    if (tid < 384) { if (tid < 384) s_w3[tid] = ow3[tid]; }
    if (tid < 64) { s_b1[tid] = ob1[tid]; s_b2[tid] = ob2[tid]; }
    if (tid < 6)  s_b3[tid] = ob3[tid];
    for (int i = tid; i < 768; i += 384) {
        int r = i >> 8, k = i & 255;
        int b = b0 + r;
        s_h[i] = (b < BATCH) ? g_gruh[b * HID + k] : 0.f;
    }
    if (tid < 24) s_x[tid] = 0.f;
    __syncthreads();

    // decode horizon robustly (int32 or float32-encoded)
    int T = 50;
    if (horizon_p) {
        int v = *horizon_p;
        if (v > 0 && v <= 1000000) T = v;
        else {
            float fv = __int_as_float(v);
            if (fv > 0.f && fv <= 1000000.f) T = (int)fv;
        }
    }
    const int off2 = out_size >> 1;

    const int g  = tid % 192;      // float4 group over j (768 = 192*4)
    const int kh = tid / 192;      // k-half
    const int kbase = kh * 128;

    for (int t = 0; t < T; ++t) {
        // ---- gh = h @ W_hh^T + b_hh (via transposed weights, coalesced) ----
        float4 a0 = {0,0,0,0}, a1 = {0,0,0,0}, a2 = {0,0,0,0};
        const float* Wp = g_WhhT + (size_t)kbase * 768 + g * 4;
        #pragma unroll 4
        for (int k = 0; k < 128; ++k) {
            float4 w = *(const float4*)(Wp + (size_t)k * 768);
            float h0 = s_h[kbase + k], h1 = s_h[256 + kbase + k], h2 = s_h[512 + kbase + k];
            a0.x += w.x*h0; a0.y += w.y*h0; a0.z += w.z*h0; a0.w += w.w*h0;
            a1.x += w.x*h1; a1.y += w.y*h1; a1.z += w.z*h1; a1.w += w.w*h1;
            a2.x += w.x*h2; a2.y += w.y*h2; a2.z += w.z*h2; a2.w += w.w*h2;
        }
        if (kh == 1) {
            *(float4*)&s_pt[0*768 + g*4] = a0;
            *(float4*)&s_pt[1*768 + g*4] = a1;
            *(float4*)&s_pt[2*768 + g*4] = a2;
        }
        __syncthreads();
        if (kh == 0) {
            float4 bb = *(float4*)&s_bhh[g*4];
            float4 p0 = *(float4*)&s_pt[0*768 + g*4];
            float4 p1 = *(float4*)&s_pt[1*768 + g*4];
            float4 p2 = *(float4*)&s_pt[2*768 + g*4];
            float4 r0 = {a0.x+p0.x+bb.x, a0.y+p0.y+bb.y, a0.z+p0.z+bb.z, a0.w+p0.w+bb.w};
            float4 r1 = {a1.x+p1.x+bb.x, a1.y+p1.y+bb.y, a1.z+p1.z+bb.z, a1.w+p1.w+bb.w};
            float4 r2 = {a2.x+p2.x+bb.x, a2.y+p2.y+bb.y, a2.z+p2.z+bb.z, a2.w+p2.w+bb.w};
            *(float4*)&s_gh[0*768 + g*4] = r0;
            *(float4*)&s_gh[1*768 + g*4] = r1;
            *(float4*)&s_gh[2*768 + g*4] = r2;
        }
        __syncthreads();

        // ---- gates + h update ----
        #pragma unroll
        for (int it = 0; it < 2; ++it) {
            int item = tid + it * 384;
            int r = item >> 8, kk = item & 255;
            float x0 = s_x[r*8+0], x1 = s_x[r*8+1], x2 = s_x[r*8+2];
            float x3 = s_x[r*8+3], x4 = s_x[r*8+4], x5 = s_x[r*8+5];
            const float* wr = s_Wih + kk * 6;
            const float* wz = s_Wih + (256 + kk) * 6;
            const float* wn = s_Wih + (512 + kk) * 6;
            float gir = s_bih[kk]       + x0*wr[0]+x1*wr[1]+x2*wr[2]+x3*wr[3]+x4*wr[4]+x5*wr[5];
            float giz = s_bih[256 + kk] + x0*wz[0]+x1*wz[1]+x2*wz[2]+x3*wz[3]+x4*wz[4]+x5*wz[5];
            float gin = s_bih[512 + kk] + x0*wn[0]+x1*wn[1]+x2*wn[2]+x3*wn[3]+x4*wn[4]+x5*wn[5];
            float rr = sigf(gir + s_gh[r*768 + kk]);
            float zz = sigf(giz + s_gh[r*768 + 256 + kk]);
            float nn = tanhfast(gin + rr * s_gh[r*768 + 512 + kk]);
            float hn = (1.f - zz) * nn + zz * s_h[r*256 + kk];
            s_h[r*256 + kk] = hn;
        }
        __syncthreads();

        // ---- out MLP: 256 -> 64 -> 64 -> 6 ----
        if (tid < 192) {
            int r = tid >> 6, j = tid & 63;
            float a = s_b1[j];
            const float* hb = s_h + r * 256;
            #pragma unroll 4
            for (int k = 0; k < 256; ++k) a += hb[k] * s_w1[k * 64 + j];
            s_o1[r*64 + j] = fmaxf(a, 0.f);
        }
        __syncthreads();
        if (tid < 192) {
            int r = tid >> 6, j = tid & 63;
            float a = s_b2[j];
            #pragma unroll 4
            for (int k = 0; k < 64; ++k) a += s_o1[r*64 + k] * s_w2[k * 64 + j];
            s_o2[r*64 + j] = fmaxf(a, 0.f);
        }
        __syncthreads();
        if (tid < 18) {
            int r = tid / 6, a = tid % 6;
            float d = s_b3[a];
            #pragma unroll 4
            for (int k = 0; k < 64; ++k) d += s_o2[r*64 + k] * s_w3[k * 6 + a];
            float xn = s_x[r*8 + a] + d;
            s_x[r*8 + a] = xn;
            int b = b0 + r;
            if (b < BATCH) {
                size_t o = ((size_t)b * T + t) * 6 + a;
                out[o] = d;            // dws
                out[off2 + o] = xn;    // ws
            }
        }
        __syncthreads();
    }
}

// ---------------------------------------------------------------------------
// launch
// ---------------------------------------------------------------------------
extern "C" void kernel_launch(void* const* d_in, const int* in_sizes, int n_in,
                              void* d_out, int out_size)
{
    // Locate horizon (unique size-1 input); remaining inputs keep their
    // relative order in both plausible metadata orderings.
    int hpos = -1;
    for (int i = 0; i < n_in; ++i) if (in_sizes[i] == 1) hpos = i;

    const float* ins[23];
    int j = 0;
    for (int i = 0; i < n_in && j < 23; ++i) {
        if (i == hpos) continue;
        ins[j++] = (const float*)d_in[i];
    }
    const int* hp = (hpos >= 0) ? (const int*)d_in[hpos] : nullptr;

    // ins: 0 data | 1 enc_w1 2 enc_b1 3 enc_w2 4 enc_b2 5 enc_w3 6 enc_b3
    //      7 mlp_w1 8 mlp_b1 9 mlp_w2 10 mlp_b2 11 mlp_w3 12 mlp_b3
    //      13 W_ih 14 W_hh 15 b_ih 16 b_hh
    //      17 out_w1 18 out_b1 19 out_w2 20 out_b2 21 out_w3 22 out_b3

    const int enc_smem = ENC_SMEM_FLOATS * 4;
    const int gru_smem = GRU_SMEM_FLOATS * 4;
    cudaFuncSetAttribute(enc_kernel, cudaFuncAttributeMaxDynamicSharedMemorySize, enc_smem);
    cudaFuncSetAttribute(gru_kernel, cudaFuncAttributeMaxDynamicSharedMemorySize, gru_smem);

    zero_feat_kernel<<<512, 256>>>();
    transpose_whh_kernel<<<768, 256>>>(ins[14]);
    enc_kernel<<<dim3(8, 256), 256, enc_smem>>>(ins[0], ins[1], ins[2], ins[3], ins[4], ins[5], ins[6]);
    head_kernel<<<256, 256>>>(ins[7], ins[8], ins[9], ins[10], ins[11], ins[12]);
    gru_kernel<<<86, 384, gru_smem>>>(ins[13], ins[15], ins[16],
                                      ins[17], ins[18], ins[19], ins[20], ins[21], ins[22],
                                      hp, (float*)d_out, out_size);
}

// round 4
// speedup vs baseline: 1.1700x; 1.1700x over previous
#include <cuda_runtime.h>
#include <cuda_bf16.h>
#include <cstdint>
#include <cstddef>

// ---------------------------------------------------------------------------
// Problem constants
// ---------------------------------------------------------------------------
#define BATCH   256
#define NPTS    1024
#define HID     256
#define ACT     6

// device scratch
__device__ float g_feat[BATCH * 512];    // pooled PointNet feature
__device__ float g_gruh[BATCH * HID];    // initial GRU hidden state
__device__ float g_WhhT[HID * 768];      // W_hh transposed to [k][j]

// ---------------------------------------------------------------------------
// helpers
// ---------------------------------------------------------------------------
__device__ __forceinline__ unsigned f2tf(float x) {
    unsigned u; asm("cvt.rna.tf32.f32 %0, %1;" : "=r"(u) : "f"(x)); return u;
}

__device__ __forceinline__ void mma_tf32(float* d, const unsigned* a, const unsigned* b) {
    asm volatile(
        "mma.sync.aligned.m16n8k8.row.col.f32.tf32.tf32.f32 "
        "{%0,%1,%2,%3}, {%4,%5,%6,%7}, {%8,%9}, {%0,%1,%2,%3};\n"
        : "+f"(d[0]), "+f"(d[1]), "+f"(d[2]), "+f"(d[3])
        : "r"(a[0]), "r"(a[1]), "r"(a[2]), "r"(a[3]), "r"(b[0]), "r"(b[1]));
}

#define FMA2(d, a, b) asm volatile("fma.rn.f32x2 %0, %1, %2, %0;" : "+l"(d) : "l"(a), "l"(b))

union U64F2 { unsigned long long u; float2 f; };

__device__ __forceinline__ float sigf(float x) { return 1.f / (1.f + __expf(-x)); }
__device__ __forceinline__ float tanhfast(float x) { return 2.f / (1.f + __expf(-2.f * x)) - 1.f; }

// ---------------------------------------------------------------------------
// zero the feature accumulator (maxpool identity = 0 since post-relu >= 0)
// ---------------------------------------------------------------------------
__global__ void zero_feat_kernel() {
    int i = blockIdx.x * 256 + threadIdx.x;
    g_feat[i] = 0.f;
}

// ---------------------------------------------------------------------------
// transpose W_hh [768,256] -> g_WhhT [256,768]
// ---------------------------------------------------------------------------
__global__ void transpose_whh_kernel(const float* __restrict__ Whh) {
    int idx = blockIdx.x * 256 + threadIdx.x;
    int k = idx / 768;
    int j = idx - k * 768;
    g_WhhT[idx] = Whh[j * 256 + k];
}

// ---------------------------------------------------------------------------
// Fused PointNet encoder: 3->64->128 (fp32 SIMT) -> 512 (tf32 tensor cores)
// grid (8 chunks, 256 batches), 256 threads, block handles 128 points
// ---------------------------------------------------------------------------
#define ENC_HP_LD 132
#define ENC_SW_LD 136
// Hp(128*132=16896) + max(rA 16384, sW 128*136=17408 + sRed 512)
#define ENC_SMEM_FLOATS (16896 + 17920)

__global__ void __launch_bounds__(256) enc_kernel(
    const float* __restrict__ data,
    const float* __restrict__ w1, const float* __restrict__ b1,
    const float* __restrict__ w2, const float* __restrict__ b2,
    const float* __restrict__ w3, const float* __restrict__ b3)
{
    extern __shared__ float sm[];
    float* Hp   = sm;                    // layer-2 output (tf32 bits), [i][k] LD=132
    float* work = sm + 16896;
    float* rA   = work;                  // phase A/B: H64T[64][128] + W2[64][128]
    float* sW   = work;                  // phase C: W3 chunk [128][136] tf32
    float* sRed = work + 17408;          // 4x128 warp-row maxes
    __shared__ float sPts[128 * 3];

    const int tid   = threadIdx.x;
    const int b     = blockIdx.y;
    const int chunk = blockIdx.x;

    // ---- load 128 points + stage W2 ----
    const float* dptr = data + (size_t)(b * NPTS + chunk * 128) * 3;
    for (int i = tid; i < 384; i += 256) sPts[i] = dptr[i];
    for (int i = tid * 4; i < 8192; i += 1024)
        *(float4*)(rA + 8192 + i) = *(const float4*)(w2 + i);
    __syncthreads();

    // ---- layer 1: H64T[k][i] = relu(p . w1col + b1) ----
    #pragma unroll
    for (int it = 0; it < 32; ++it) {
        int idx = tid + it * 256;
        int k = idx >> 7, i = idx & 127;
        float v = b1[k] + sPts[i*3] * w1[k] + sPts[i*3+1] * w1[64 + k] + sPts[i*3+2] * w1[128 + k];
        rA[idx] = fmaxf(v, 0.f);
    }
    __syncthreads();

    const int ty = tid >> 4, tx = tid & 15;
    const int i0 = ty * 8, j0 = tx * 8;

    // ---- layer 2 (fp32 8x8 microkernel) -> Hp[i][k] as tf32 bits ----
    {
        float acc[8][8];
        #pragma unroll
        for (int a = 0; a < 8; ++a)
            #pragma unroll
            for (int c = 0; c < 8; ++c) acc[a][c] = 0.f;

        #pragma unroll 4
        for (int k = 0; k < 64; ++k) {
            float av[8], wv[8];
            *(float4*)&av[0] = *(float4*)(rA + k*128 + i0);
            *(float4*)&av[4] = *(float4*)(rA + k*128 + i0 + 4);
            *(float4*)&wv[0] = *(float4*)(rA + 8192 + k*128 + j0);
            *(float4*)&wv[4] = *(float4*)(rA + 8192 + k*128 + j0 + 4);
            #pragma unroll
            for (int a = 0; a < 8; ++a)
                #pragma unroll
                for (int c = 0; c < 8; ++c) acc[a][c] += av[a] * wv[c];
        }
        float bj[8];
        #pragma unroll
        for (int c = 0; c < 8; ++c) bj[c] = b2[j0 + c];
        unsigned* Hpu = (unsigned*)Hp;
        #pragma unroll
        for (int a = 0; a < 8; ++a) {
            unsigned uv[8];
            #pragma unroll
            for (int c = 0; c < 8; ++c)
                uv[c] = f2tf(fmaxf(acc[a][c] + bj[c], 0.f));
            uint4 v0 = make_uint4(uv[0], uv[1], uv[2], uv[3]);
            uint4 v1 = make_uint4(uv[4], uv[5], uv[6], uv[7]);
            *(uint4*)(Hpu + (i0 + a) * ENC_HP_LD + j0) = v0;
            *(uint4*)(Hpu + (i0 + a) * ENC_HP_LD + j0 + 4) = v1;
        }
    }
    __syncthreads();

    // ---- layer 3 via tf32 mma: [128 pts] x [512 out], K=128, 4 N-chunks ----
    const int lane = tid & 31, wrp = tid >> 5;
    const int wm = wrp & 3, wn = wrp >> 2;    // 4 M-groups x 2 N-halves
    const int qp = lane >> 2, rr = lane & 3;
    const unsigned* Hpu = (const unsigned*)Hp;
    unsigned* sWu = (unsigned*)sW;

    for (int nc = 0; nc < 4; ++nc) {
        // stage W3 chunk (tf32)
        for (int idx = tid; idx < 16384; idx += 256) {
            int k = idx >> 7, n = idx & 127;
            sWu[k * ENC_SW_LD + n] = f2tf(w3[(size_t)k * 512 + nc * 128 + n]);
        }
        __syncthreads();

        float acc[2][8][4];
        #pragma unroll
        for (int mt = 0; mt < 2; ++mt)
            #pragma unroll
            for (int nt = 0; nt < 8; ++nt)
                #pragma unroll
                for (int q = 0; q < 4; ++q) acc[mt][nt][q] = 0.f;

        #pragma unroll 1
        for (int ks = 0; ks < 16; ++ks) {
            int k0 = ks * 8;
            unsigned af[2][4];
            #pragma unroll
            for (int mt = 0; mt < 2; ++mt) {
                int r0 = wm * 32 + mt * 16 + qp;
                af[mt][0] = Hpu[r0 * ENC_HP_LD + k0 + rr];
                af[mt][1] = Hpu[(r0 + 8) * ENC_HP_LD + k0 + rr];
                af[mt][2] = Hpu[r0 * ENC_HP_LD + k0 + rr + 4];
                af[mt][3] = Hpu[(r0 + 8) * ENC_HP_LD + k0 + rr + 4];
            }
            unsigned bf[8][2];
            #pragma unroll
            for (int nt = 0; nt < 8; ++nt) {
                int n = wn * 64 + nt * 8 + qp;
                bf[nt][0] = sWu[(k0 + rr) * ENC_SW_LD + n];
                bf[nt][1] = sWu[(k0 + 4 + rr) * ENC_SW_LD + n];
            }
            #pragma unroll
            for (int mt = 0; mt < 2; ++mt)
                #pragma unroll
                for (int nt = 0; nt < 8; ++nt)
                    mma_tf32(acc[mt][nt], af[mt], bf[nt]);
        }

        // epilogue: bias + relu + column max over 32 rows, then cross-warp
        #pragma unroll
        for (int nt = 0; nt < 8; ++nt) {
            int n = wn * 64 + nt * 8 + 2 * rr;
            float bv0 = b3[nc * 128 + n];
            float bv1 = b3[nc * 128 + n + 1];
            float m0 = 0.f, m1 = 0.f;
            #pragma unroll
            for (int mt = 0; mt < 2; ++mt) {
                float* d = acc[mt][nt];
                m0 = fmaxf(m0, fmaxf(d[0] + bv0, d[2] + bv0));
                m1 = fmaxf(m1, fmaxf(d[1] + bv1, d[3] + bv1));
            }
            #pragma unroll
            for (int s = 4; s < 32; s <<= 1) {
                m0 = fmaxf(m0, __shfl_xor_sync(0xffffffffu, m0, s));
                m1 = fmaxf(m1, __shfl_xor_sync(0xffffffffu, m1, s));
            }
            if (qp == 0) {
                sRed[wm * 128 + n]     = m0;
                sRed[wm * 128 + n + 1] = m1;
            }
        }
        __syncthreads();
        if (tid < 128) {
            float m = fmaxf(fmaxf(sRed[tid], sRed[128 + tid]),
                            fmaxf(sRed[256 + tid], sRed[384 + tid]));
            atomicMax((int*)&g_feat[b * 512 + nc * 128 + tid], __float_as_int(m));
        }
        __syncthreads();
    }
}

// ---------------------------------------------------------------------------
// Head MLP: 512 -> 256 -> 128 -> 256 (4-acc ILP)
// ---------------------------------------------------------------------------
__global__ void __launch_bounds__(256) head_kernel(
    const float* __restrict__ w1, const float* __restrict__ b1,
    const float* __restrict__ w2, const float* __restrict__ b2,
    const float* __restrict__ w3, const float* __restrict__ b3)
{
    __shared__ float sh[512];
    __shared__ float s1[256];
    __shared__ float s2[128];
    int b = blockIdx.x, tid = threadIdx.x;
    sh[tid]       = g_feat[b * 512 + tid];
    sh[tid + 256] = g_feat[b * 512 + 256 + tid];
    __syncthreads();
    {
        float a0 = 0, a1 = 0, a2 = 0, a3 = 0;
        const float* wp = w1 + tid;
        #pragma unroll 8
        for (int k = 0; k < 512; k += 4) {
            a0 += sh[k]     * wp[(size_t)k * 256];
            a1 += sh[k + 1] * wp[(size_t)(k + 1) * 256];
            a2 += sh[k + 2] * wp[(size_t)(k + 2) * 256];
            a3 += sh[k + 3] * wp[(size_t)(k + 3) * 256];
        }
        s1[tid] = fmaxf(b1[tid] + (a0 + a1) + (a2 + a3), 0.f);
    }
    __syncthreads();
    if (tid < 128) {
        float a0 = 0, a1 = 0, a2 = 0, a3 = 0;
        const float* wp = w2 + tid;
        #pragma unroll 8
        for (int k = 0; k < 256; k += 4) {
            a0 += s1[k]     * wp[k * 128];
            a1 += s1[k + 1] * wp[(k + 1) * 128];
            a2 += s1[k + 2] * wp[(k + 2) * 128];
            a3 += s1[k + 3] * wp[(k + 3) * 128];
        }
        s2[tid] = fmaxf(b2[tid] + (a0 + a1) + (a2 + a3), 0.f);
    }
    __syncthreads();
    {
        float a0 = 0, a1 = 0, a2 = 0, a3 = 0;
        const float* wp = w3 + tid;
        #pragma unroll 8
        for (int k = 0; k < 128; k += 4) {
            a0 += s2[k]     * wp[k * 256];
            a1 += s2[k + 1] * wp[(k + 1) * 256];
            a2 += s2[k + 2] * wp[(k + 2) * 256];
            a3 += s2[k + 3] * wp[(k + 3) * 256];
        }
        g_gruh[b * HID + tid] = b3[tid] + (a0 + a1) + (a2 + a3);
    }
}

// ---------------------------------------------------------------------------
// GRU rollout: 64 blocks x 4 batch rows, 384 threads, packed f32x2 FMA
// ---------------------------------------------------------------------------
#define GRU_SMEM_FLOATS 36904

__global__ void __launch_bounds__(384) gru_kernel(
    const float* __restrict__ Wih, const float* __restrict__ bih, const float* __restrict__ bhh,
    const float* __restrict__ ow1, const float* __restrict__ ob1,
    const float* __restrict__ ow2, const float* __restrict__ ob2,
    const float* __restrict__ ow3, const float* __restrict__ ob3,
    const int* __restrict__ horizon_p, float* __restrict__ out, int out_size)
{
    extern __shared__ float sm[];
    float* s_Wih = sm;                   // 4608
    float* s_bih = s_Wih + 4608;         // 768
    float* s_bhh = s_bih + 768;          // 768
    float* s_w1  = s_bhh + 768;          // 16384
    float* s_w2  = s_w1 + 16384;         // 4096
    float* s_w3  = s_w2 + 4096;          // 384
    float* s_b1  = s_w3 + 384;           // 64
    float* s_b2  = s_b1 + 64;            // 64
    float* s_b3  = s_b2 + 64;            // 8
    float* s_h   = s_b3 + 8;             // 1024 (4 rows x 256)
    float* s_hdf = s_h + 1024;           // 2048 (dup pairs for f32x2)
    float* s_x   = s_hdf + 2048;         // 32
    float* s_gh  = s_x + 32;             // 3072
    float* s_pt  = s_gh + 3072;          // 3072
    float* s_o1  = s_pt + 3072;          // 256
    float* s_o2  = s_o1 + 256;           // 256

    const int tid = threadIdx.x;
    const int b0  = blockIdx.x * 4;

    for (int i = tid; i < 4608;  i += 384) s_Wih[i] = Wih[i];
    for (int i = tid; i < 768;   i += 384) { s_bih[i] = bih[i]; s_bhh[i] = bhh[i]; }
    for (int i = tid; i < 16384; i += 384) s_w1[i] = ow1[i];
    for (int i = tid; i < 4096;  i += 384) s_w2[i] = ow2[i];
    if (tid < 384) s_w3[tid] = ow3[tid];
    if (tid < 64) { s_b1[tid] = ob1[tid]; s_b2[tid] = ob2[tid]; }
    if (tid < 6)  s_b3[tid] = ob3[tid];
    for (int i = tid; i < 1024; i += 384) {
        int r = i >> 8, k = i & 255;
        float hv = g_gruh[(b0 + r) * HID + k];
        s_h[i] = hv;
        s_hdf[2 * i] = hv; s_hdf[2 * i + 1] = hv;
    }
    if (tid < 32) s_x[tid] = 0.f;
    __syncthreads();

    // decode horizon robustly
    int T = 50;
    if (horizon_p) {
        int v = *horizon_p;
        if (v > 0 && v <= 1000000) T = v;
        else {
            float fv = __int_as_float(v);
            if (fv > 0.f && fv <= 1000000.f) T = (int)fv;
        }
    }
    const int off2 = out_size >> 1;

    const int g  = tid % 192;      // float4 group over j (768 = 192*4)
    const int kh = tid / 192;      // k-half
    const int kbase = kh * 128;
    const unsigned long long* hd = (const unsigned long long*)s_hdf;

    for (int t = 0; t < T; ++t) {
        // ---- gh = h @ W_hh^T + b_hh (coalesced transposed weights, f32x2) ----
        unsigned long long acc[4][2] = {{0ULL,0ULL},{0ULL,0ULL},{0ULL,0ULL},{0ULL,0ULL}};
        const float* Wp = g_WhhT + (size_t)kbase * 768 + g * 4;
        #pragma unroll 2
        for (int k = 0; k < 128; ++k) {
            ulonglong2 w = *(const ulonglong2*)(Wp + (size_t)k * 768);
            unsigned long long h0 = hd[kbase + k];
            unsigned long long h1 = hd[256 + kbase + k];
            unsigned long long h2 = hd[512 + kbase + k];
            unsigned long long h3 = hd[768 + kbase + k];
            FMA2(acc[0][0], w.x, h0); FMA2(acc[0][1], w.y, h0);
            FMA2(acc[1][0], w.x, h1); FMA2(acc[1][1], w.y, h1);
            FMA2(acc[2][0], w.x, h2); FMA2(acc[2][1], w.y, h2);
            FMA2(acc[3][0], w.x, h3); FMA2(acc[3][1], w.y, h3);
        }
        if (kh == 1) {
            #pragma unroll
            for (int r = 0; r < 4; ++r) {
                ulonglong2 v = make_ulonglong2(acc[r][0], acc[r][1]);
                *(ulonglong2*)&s_pt[r * 768 + g * 4] = v;
            }
        }
        __syncthreads();
        if (kh == 0) {
            float4 bb = *(float4*)&s_bhh[g * 4];
            #pragma unroll
            for (int r = 0; r < 4; ++r) {
                float4 p = *(float4*)&s_pt[r * 768 + g * 4];
                U64F2 u0; u0.u = acc[r][0];
                U64F2 u1; u1.u = acc[r][1];
                float4 res = make_float4(u0.f.x + p.x + bb.x, u0.f.y + p.y + bb.y,
                                         u1.f.x + p.z + bb.z, u1.f.y + p.w + bb.w);
                *(float4*)&s_gh[r * 768 + g * 4] = res;
            }
        }
        __syncthreads();

        // ---- gates + h update (1024 items) ----
        #pragma unroll
        for (int it = 0; it < 3; ++it) {
            int item = tid + it * 384;
            if (item < 1024) {
                int r = item >> 8, kk = item & 255;
                float x0 = s_x[r*8+0], x1 = s_x[r*8+1], x2 = s_x[r*8+2];
                float x3 = s_x[r*8+3], x4 = s_x[r*8+4], x5 = s_x[r*8+5];
                const float* wr = s_Wih + kk * 6;
                const float* wz = s_Wih + (256 + kk) * 6;
                const float* wn = s_Wih + (512 + kk) * 6;
                float gir = s_bih[kk]       + x0*wr[0]+x1*wr[1]+x2*wr[2]+x3*wr[3]+x4*wr[4]+x5*wr[5];
                float giz = s_bih[256 + kk] + x0*wz[0]+x1*wz[1]+x2*wz[2]+x3*wz[3]+x4*wz[4]+x5*wz[5];
                float gin = s_bih[512 + kk] + x0*wn[0]+x1*wn[1]+x2*wn[2]+x3*wn[3]+x4*wn[4]+x5*wn[5];
                float rr = sigf(gir + s_gh[r*768 + kk]);
                float zz = sigf(giz + s_gh[r*768 + 256 + kk]);
                float nn = tanhfast(gin + rr * s_gh[r*768 + 512 + kk]);
                float hn = (1.f - zz) * nn + zz * s_h[r*256 + kk];
                s_h[r*256 + kk] = hn;
                s_hdf[2*(r*256 + kk)]     = hn;
                s_hdf[2*(r*256 + kk) + 1] = hn;
            }
        }
        __syncthreads();

        // ---- out MLP: 256 -> 64 -> 64 -> 6 ----
        if (tid < 256) {
            int r = tid >> 6, j = tid & 63;
            float a0 = 0, a1 = 0, a2 = 0, a3 = 0;
            const float* hb = s_h + r * 256;
            #pragma unroll 8
            for (int k = 0; k < 256; k += 4) {
                a0 += hb[k]     * s_w1[k * 64 + j];
                a1 += hb[k + 1] * s_w1[(k + 1) * 64 + j];
                a2 += hb[k + 2] * s_w1[(k + 2) * 64 + j];
                a3 += hb[k + 3] * s_w1[(k + 3) * 64 + j];
            }
            s_o1[tid] = fmaxf(s_b1[j] + (a0 + a1) + (a2 + a3), 0.f);
        }
        __syncthreads();
        if (tid < 256) {
            int r = tid >> 6, j = tid & 63;
            float a0 = 0, a1 = 0;
            #pragma unroll 8
            for (int k = 0; k < 64; k += 2) {
                a0 += s_o1[r*64 + k]     * s_w2[k * 64 + j];
                a1 += s_o1[r*64 + k + 1] * s_w2[(k + 1) * 64 + j];
            }
            s_o2[tid] = fmaxf(s_b2[j] + a0 + a1, 0.f);
        }
        __syncthreads();
        if (tid < 24) {
            int r = tid / 6, a = tid % 6;
            float d0 = 0, d1 = 0;
            #pragma unroll 8
            for (int k = 0; k < 64; k += 2) {
                d0 += s_o2[r*64 + k]     * s_w3[k * 6 + a];
                d1 += s_o2[r*64 + k + 1] * s_w3[(k + 1) * 6 + a];
            }
            float d = s_b3[a] + d0 + d1;
            float xn = s_x[r*8 + a] + d;
            s_x[r*8 + a] = xn;
            int b = b0 + r;
            size_t o = ((size_t)b * T + t) * 6 + a;
            out[o] = d;            // dws
            out[off2 + o] = xn;    // ws
        }
        __syncthreads();
    }
}

// ---------------------------------------------------------------------------
// launch
// ---------------------------------------------------------------------------
extern "C" void kernel_launch(void* const* d_in, const int* in_sizes, int n_in,
                              void* d_out, int out_size)
{
    // Locate horizon (unique size-1 input)
    int hpos = -1;
    for (int i = 0; i < n_in; ++i) if (in_sizes[i] == 1) hpos = i;

    const float* ins[23];
    int j = 0;
    for (int i = 0; i < n_in && j < 23; ++i) {
        if (i == hpos) continue;
        ins[j++] = (const float*)d_in[i];
    }
    const int* hp = (hpos >= 0) ? (const int*)d_in[hpos] : nullptr;

    // ins: 0 data | 1 enc_w1 2 enc_b1 3 enc_w2 4 enc_b2 5 enc_w3 6 enc_b3
    //      7 mlp_w1 8 mlp_b1 9 mlp_w2 10 mlp_b2 11 mlp_w3 12 mlp_b3
    //      13 W_ih 14 W_hh 15 b_ih 16 b_hh
    //      17 out_w1 18 out_b1 19 out_w2 20 out_b2 21 out_w3 22 out_b3

    const int enc_smem = ENC_SMEM_FLOATS * 4;
    const int gru_smem = GRU_SMEM_FLOATS * 4;
    cudaFuncSetAttribute(enc_kernel, cudaFuncAttributeMaxDynamicSharedMemorySize, enc_smem);
    cudaFuncSetAttribute(gru_kernel, cudaFuncAttributeMaxDynamicSharedMemorySize, gru_smem);

    zero_feat_kernel<<<512, 256>>>();
    transpose_whh_kernel<<<768, 256>>>(ins[14]);
    enc_kernel<<<dim3(8, 256), 256, enc_smem>>>(ins[0], ins[1], ins[2], ins[3], ins[4], ins[5], ins[6]);
    head_kernel<<<256, 256>>>(ins[7], ins[8], ins[9], ins[10], ins[11], ins[12]);
    gru_kernel<<<64, 384, gru_smem>>>(ins[13], ins[15], ins[16],
                                      ins[17], ins[18], ins[19], ins[20], ins[21], ins[22],
                                      hp, (float*)d_out, out_size);
}

// round 6
// speedup vs baseline: 1.6798x; 1.4358x over previous
#include <cuda_runtime.h>
#include <cuda_bf16.h>
#include <cstdint>
#include <cstddef>

// ---------------------------------------------------------------------------
// Problem constants
// ---------------------------------------------------------------------------
#define BATCH   256
#define NPTS    1024
#define HID     256
#define ACT     6

// device scratch
__device__ float g_feat[BATCH * 512];
__device__ float g_gruh[BATCH * HID];
__device__ float g_WhhT[HID * 768];
// GRU pair-exchange payload: [parity][block][4*384 gh + 16 x] + flags
#define GRU_BLOCKS 128
__device__ float g_pay[2][GRU_BLOCKS][1552];
__device__ int   g_flag[GRU_BLOCKS];

// ---------------------------------------------------------------------------
// helpers
// ---------------------------------------------------------------------------
__device__ __forceinline__ unsigned f2tf(float x) {
    unsigned u; asm("cvt.rna.tf32.f32 %0, %1;" : "=r"(u) : "f"(x)); return u;
}

__device__ __forceinline__ void mma_tf32(float* d, const unsigned* a, const unsigned* b) {
    asm volatile(
        "mma.sync.aligned.m16n8k8.row.col.f32.tf32.tf32.f32 "
        "{%0,%1,%2,%3}, {%4,%5,%6,%7}, {%8,%9}, {%0,%1,%2,%3};\n"
        : "+f"(d[0]), "+f"(d[1]), "+f"(d[2]), "+f"(d[3])
        : "r"(a[0]), "r"(a[1]), "r"(a[2]), "r"(a[3]), "r"(b[0]), "r"(b[1]));
}

__device__ __forceinline__ float sigf(float x) { return 1.f / (1.f + __expf(-x)); }
__device__ __forceinline__ float tanhfast(float x) { return 2.f / (1.f + __expf(-2.f * x)) - 1.f; }

// ---------------------------------------------------------------------------
// prep kernels
// ---------------------------------------------------------------------------
__global__ void zero_feat_kernel() {
    g_feat[blockIdx.x * 256 + threadIdx.x] = 0.f;
}

__global__ void transpose_whh_kernel(const float* __restrict__ Whh) {
    int idx = blockIdx.x * 256 + threadIdx.x;
    int k = idx / 768, j = idx - k * 768;
    g_WhhT[idx] = Whh[j * 256 + k];
}

__global__ void zero_flags_kernel() {
    if (threadIdx.x < GRU_BLOCKS) g_flag[threadIdx.x] = 0;
}

// ---------------------------------------------------------------------------
// Fused PointNet encoder: 3->64->128 (fp32 SIMT) -> 512 (tf32 tensor cores)
// grid (8 chunks, 256 batches), 256 threads, block handles 128 points
// (identical to the R4 passing version)
// ---------------------------------------------------------------------------
#define ENC_HP_LD 132
#define ENC_SW_LD 136
#define ENC_SMEM_FLOATS (16896 + 17920)

__global__ void __launch_bounds__(256) enc_kernel(
    const float* __restrict__ data,
    const float* __restrict__ w1, const float* __restrict__ b1,
    const float* __restrict__ w2, const float* __restrict__ b2,
    const float* __restrict__ w3, const float* __restrict__ b3)
{
    extern __shared__ float sm[];
    float* Hp   = sm;
    float* work = sm + 16896;
    float* rA   = work;
    float* sW   = work;
    float* sRed = work + 17408;
    __shared__ float sPts[128 * 3];

    const int tid   = threadIdx.x;
    const int b     = blockIdx.y;
    const int chunk = blockIdx.x;

    const float* dptr = data + (size_t)(b * NPTS + chunk * 128) * 3;
    for (int i = tid; i < 384; i += 256) sPts[i] = dptr[i];
    for (int i = tid * 4; i < 8192; i += 1024)
        *(float4*)(rA + 8192 + i) = *(const float4*)(w2 + i);
    __syncthreads();

    #pragma unroll
    for (int it = 0; it < 32; ++it) {
        int idx = tid + it * 256;
        int k = idx >> 7, i = idx & 127;
        float v = b1[k] + sPts[i*3] * w1[k] + sPts[i*3+1] * w1[64 + k] + sPts[i*3+2] * w1[128 + k];
        rA[idx] = fmaxf(v, 0.f);
    }
    __syncthreads();

    const int ty = tid >> 4, tx = tid & 15;
    const int i0 = ty * 8, j0 = tx * 8;

    {
        float acc[8][8];
        #pragma unroll
        for (int a = 0; a < 8; ++a)
            #pragma unroll
            for (int c = 0; c < 8; ++c) acc[a][c] = 0.f;

        #pragma unroll 4
        for (int k = 0; k < 64; ++k) {
            float av[8], wv[8];
            *(float4*)&av[0] = *(float4*)(rA + k*128 + i0);
            *(float4*)&av[4] = *(float4*)(rA + k*128 + i0 + 4);
            *(float4*)&wv[0] = *(float4*)(rA + 8192 + k*128 + j0);
            *(float4*)&wv[4] = *(float4*)(rA + 8192 + k*128 + j0 + 4);
            #pragma unroll
            for (int a = 0; a < 8; ++a)
                #pragma unroll
                for (int c = 0; c < 8; ++c) acc[a][c] += av[a] * wv[c];
        }
        float bj[8];
        #pragma unroll
        for (int c = 0; c < 8; ++c) bj[c] = b2[j0 + c];
        unsigned* Hpu = (unsigned*)Hp;
        #pragma unroll
        for (int a = 0; a < 8; ++a) {
            unsigned uv[8];
            #pragma unroll
            for (int c = 0; c < 8; ++c)
                uv[c] = f2tf(fmaxf(acc[a][c] + bj[c], 0.f));
            uint4 v0 = make_uint4(uv[0], uv[1], uv[2], uv[3]);
            uint4 v1 = make_uint4(uv[4], uv[5], uv[6], uv[7]);
            *(uint4*)(Hpu + (i0 + a) * ENC_HP_LD + j0) = v0;
            *(uint4*)(Hpu + (i0 + a) * ENC_HP_LD + j0 + 4) = v1;
        }
    }
    __syncthreads();

    const int lane = tid & 31, wrp = tid >> 5;
    const int wm = wrp & 3, wn = wrp >> 2;
    const int qp = lane >> 2, rr = lane & 3;
    const unsigned* Hpu = (const unsigned*)Hp;
    unsigned* sWu = (unsigned*)sW;

    for (int nc = 0; nc < 4; ++nc) {
        for (int idx = tid; idx < 16384; idx += 256) {
            int k = idx >> 7, n = idx & 127;
            sWu[k * ENC_SW_LD + n] = f2tf(w3[(size_t)k * 512 + nc * 128 + n]);
        }
        __syncthreads();

        float acc[2][8][4];
        #pragma unroll
        for (int mt = 0; mt < 2; ++mt)
            #pragma unroll
            for (int nt = 0; nt < 8; ++nt)
                #pragma unroll
                for (int q = 0; q < 4; ++q) acc[mt][nt][q] = 0.f;

        #pragma unroll 1
        for (int ks = 0; ks < 16; ++ks) {
            int k0 = ks * 8;
            unsigned af[2][4];
            #pragma unroll
            for (int mt = 0; mt < 2; ++mt) {
                int r0 = wm * 32 + mt * 16 + qp;
                af[mt][0] = Hpu[r0 * ENC_HP_LD + k0 + rr];
                af[mt][1] = Hpu[(r0 + 8) * ENC_HP_LD + k0 + rr];
                af[mt][2] = Hpu[r0 * ENC_HP_LD + k0 + rr + 4];
                af[mt][3] = Hpu[(r0 + 8) * ENC_HP_LD + k0 + rr + 4];
            }
            unsigned bf[8][2];
            #pragma unroll
            for (int nt = 0; nt < 8; ++nt) {
                int n = wn * 64 + nt * 8 + qp;
                bf[nt][0] = sWu[(k0 + rr) * ENC_SW_LD + n];
                bf[nt][1] = sWu[(k0 + 4 + rr) * ENC_SW_LD + n];
            }
            #pragma unroll
            for (int mt = 0; mt < 2; ++mt)
                #pragma unroll
                for (int nt = 0; nt < 8; ++nt)
                    mma_tf32(acc[mt][nt], af[mt], bf[nt]);
        }

        #pragma unroll
        for (int nt = 0; nt < 8; ++nt) {
            int n = wn * 64 + nt * 8 + 2 * rr;
            float bv0 = b3[nc * 128 + n];
            float bv1 = b3[nc * 128 + n + 1];
            float m0 = 0.f, m1 = 0.f;
            #pragma unroll
            for (int mt = 0; mt < 2; ++mt) {
                float* d = acc[mt][nt];
                m0 = fmaxf(m0, fmaxf(d[0] + bv0, d[2] + bv0));
                m1 = fmaxf(m1, fmaxf(d[1] + bv1, d[3] + bv1));
            }
            #pragma unroll
            for (int s = 4; s < 32; s <<= 1) {
                m0 = fmaxf(m0, __shfl_xor_sync(0xffffffffu, m0, s));
                m1 = fmaxf(m1, __shfl_xor_sync(0xffffffffu, m1, s));
            }
            if (qp == 0) {
                sRed[wm * 128 + n]     = m0;
                sRed[wm * 128 + n + 1] = m1;
            }
        }
        __syncthreads();
        if (tid < 128) {
            float m = fmaxf(fmaxf(sRed[tid], sRed[128 + tid]),
                            fmaxf(sRed[256 + tid], sRed[384 + tid]));
            atomicMax((int*)&g_feat[b * 512 + nc * 128 + tid], __float_as_int(m));
        }
        __syncthreads();
    }
}

// ---------------------------------------------------------------------------
// Head MLP: 512 -> 256 -> 128 -> 256, 512 threads, k-split + smem combine
// ---------------------------------------------------------------------------
__global__ void __launch_bounds__(512) head_kernel(
    const float* __restrict__ w1, const float* __restrict__ b1,
    const float* __restrict__ w2, const float* __restrict__ b2,
    const float* __restrict__ w3, const float* __restrict__ b3)
{
    __shared__ float sh[512];
    __shared__ float pp[512];
    __shared__ float s1[256];
    __shared__ float s2[128];
    int b = blockIdx.x, tid = threadIdx.x;
    sh[tid] = g_feat[b * 512 + tid];
    __syncthreads();
    {
        int j = tid & 255, half = tid >> 8, k0 = half * 256;
        const float* wp = w1 + (size_t)k0 * 256 + j;
        float a0 = 0, a1 = 0, a2 = 0, a3 = 0;
        #pragma unroll 8
        for (int k = 0; k < 256; k += 4) {
            a0 += sh[k0 + k]     * wp[(size_t)k * 256];
            a1 += sh[k0 + k + 1] * wp[(size_t)(k + 1) * 256];
            a2 += sh[k0 + k + 2] * wp[(size_t)(k + 2) * 256];
            a3 += sh[k0 + k + 3] * wp[(size_t)(k + 3) * 256];
        }
        pp[tid] = (a0 + a1) + (a2 + a3);
    }
    __syncthreads();
    if (tid < 256) s1[tid] = fmaxf(b1[tid] + pp[tid] + pp[tid + 256], 0.f);
    __syncthreads();
    {
        int j = tid & 127, q = tid >> 7, k0 = q * 64;
        const float* wp = w2 + k0 * 128 + j;
        float a0 = 0, a1 = 0;
        #pragma unroll 8
        for (int k = 0; k < 64; k += 2) {
            a0 += s1[k0 + k]     * wp[k * 128];
            a1 += s1[k0 + k + 1] * wp[(k + 1) * 128];
        }
        pp[tid] = a0 + a1;
    }
    __syncthreads();
    if (tid < 128) s2[tid] = fmaxf(b2[tid] + pp[tid] + pp[tid + 128] + pp[tid + 256] + pp[tid + 384], 0.f);
    __syncthreads();
    {
        int j = tid & 255, half = tid >> 8, k0 = half * 64;
        const float* wp = w3 + k0 * 256 + j;
        float a0 = 0, a1 = 0;
        #pragma unroll 8
        for (int k = 0; k < 64; k += 2) {
            a0 += s2[k0 + k]     * wp[k * 256];
            a1 += s2[k0 + k + 1] * wp[(k + 1) * 256];
        }
        pp[tid] = a0 + a1;
    }
    __syncthreads();
    if (tid < 256) g_gruh[b * HID + tid] = b3[tid] + pp[tid] + pp[tid + 256];
}

// ---------------------------------------------------------------------------
// GRU rollout v3: 128 blocks = 64 pairs; each pair shares 4 batch rows and
// splits the gh GEMM j-dim in half; halves exchange via L2 payload + flag.
// 384 threads/block.
// ---------------------------------------------------------------------------
#define GRU_SMEM_FLOATS 36392

__global__ void __launch_bounds__(384) gru_kernel(
    const float* __restrict__ Wih, const float* __restrict__ bih, const float* __restrict__ bhh,
    const float* __restrict__ ow1, const float* __restrict__ ob1,
    const float* __restrict__ ow2, const float* __restrict__ ob2,
    const float* __restrict__ ow3, const float* __restrict__ ob3,
    const int* __restrict__ horizon_p, float* __restrict__ out, int out_size)
{
    extern __shared__ float sm[];
    float* s_Wih  = sm;                   // 4608
    float* s_bih  = s_Wih + 4608;         // 768
    float* s_bhh  = s_bih + 768;          // 768
    float* s_w1   = s_bhh + 768;          // 16384
    float* s_w2   = s_w1 + 16384;         // 4096
    float* s_w3   = s_w2 + 4096;          // 384
    float* s_b1   = s_w3 + 384;           // 64
    float* s_b2   = s_b1 + 64;            // 64
    float* s_b3   = s_b2 + 64;            // 8
    float* s_h    = s_b3 + 8;             // 1024 (4 rows x 256)
    float* s_x    = s_h + 1024;           // 32 (4 rows x 8)
    float* s_gh   = s_x + 32;             // 3072 (4 rows x 768, full, assembled)
    float* s_part = s_gh + 3072;          // 4608 (3 k-slices x 96 jg x 16)
    float* s_p1   = s_part + 4608;        // 256
    float* s_o1   = s_p1 + 256;           // 128 (2 rows x 64)
    float* s_o2   = s_o1 + 128;           // 128

    const int tid     = threadIdx.x;
    const int bid     = blockIdx.x;
    const int pairid  = bid >> 1;
    const int half    = bid & 1;
    const int partner = bid ^ 1;
    const int b0      = pairid * 4;

    for (int i = tid; i < 4608;  i += 384) s_Wih[i] = Wih[i];
    for (int i = tid; i < 768;   i += 384) { s_bih[i] = bih[i]; s_bhh[i] = bhh[i]; }
    for (int i = tid; i < 16384; i += 384) s_w1[i] = ow1[i];
    for (int i = tid; i < 4096;  i += 384) s_w2[i] = ow2[i];
    if (tid < 384) s_w3[tid] = ow3[tid];
    if (tid < 64) { s_b1[tid] = ob1[tid]; s_b2[tid] = ob2[tid]; }
    if (tid < 6)  s_b3[tid] = ob3[tid];
    for (int i = tid; i < 1024; i += 384) {
        int r = i >> 8, k = i & 255;
        s_h[i] = g_gruh[(b0 + r) * HID + k];
    }
    if (tid < 32) s_x[tid] = 0.f;
    __syncthreads();

    int T = 50;
    if (horizon_p) {
        int v = *horizon_p;
        if (v > 0 && v <= 1000000) T = v;
        else {
            float fv = __int_as_float(v);
            if (fv > 0.f && fv <= 1000000.f) T = (int)fv;
        }
    }
    const int off2 = out_size >> 1;

    // gh GEMM mapping: 96 j-groups (float4) x 4 k-slices of 64
    const int jg   = tid % 96;
    const int ks   = tid / 96;
    const int k0   = ks * 64;
    const int jcol = half * 384 + jg * 4;
    const float* Wcol = g_WhhT + jcol;

    for (int t = 0; t < T; ++t) {
        const int par = t & 1;
        float* pay_out = &g_pay[par][bid][0];
        const float* pay_in = &g_pay[par][partner][0];

        // ---- gh-half GEMM: acc[r][c] over own k-slice ----
        float acc[4][4];
        #pragma unroll
        for (int r = 0; r < 4; ++r)
            #pragma unroll
            for (int c = 0; c < 4; ++c) acc[r][c] = 0.f;

        #pragma unroll 2
        for (int kk = 0; kk < 64; kk += 4) {
            float4 h0 = *(float4*)&s_h[0 * 256 + k0 + kk];
            float4 h1 = *(float4*)&s_h[1 * 256 + k0 + kk];
            float4 h2 = *(float4*)&s_h[2 * 256 + k0 + kk];
            float4 h3 = *(float4*)&s_h[3 * 256 + k0 + kk];
            const float* wb = Wcol + (size_t)(k0 + kk) * 768;
            #pragma unroll
            for (int q = 0; q < 4; ++q) {
                float4 w = *(const float4*)(wb + (size_t)q * 768);
                float a0 = (q == 0) ? h0.x : (q == 1) ? h0.y : (q == 2) ? h0.z : h0.w;
                float a1 = (q == 0) ? h1.x : (q == 1) ? h1.y : (q == 2) ? h1.z : h1.w;
                float a2 = (q == 0) ? h2.x : (q == 1) ? h2.y : (q == 2) ? h2.z : h2.w;
                float a3 = (q == 0) ? h3.x : (q == 1) ? h3.y : (q == 2) ? h3.z : h3.w;
                acc[0][0] += a0*w.x; acc[0][1] += a0*w.y; acc[0][2] += a0*w.z; acc[0][3] += a0*w.w;
                acc[1][0] += a1*w.x; acc[1][1] += a1*w.y; acc[1][2] += a1*w.z; acc[1][3] += a1*w.w;
                acc[2][0] += a2*w.x; acc[2][1] += a2*w.y; acc[2][2] += a2*w.z; acc[2][3] += a2*w.w;
                acc[3][0] += a3*w.x; acc[3][1] += a3*w.y; acc[3][2] += a3*w.z; acc[3][3] += a3*w.w;
            }
        }

        // ---- reduce k-slices ----
        if (ks > 0) {
            float* p = &s_part[((ks - 1) * 96 + jg) * 16];
            #pragma unroll
            for (int r = 0; r < 4; ++r)
                *(float4*)(p + r * 4) = make_float4(acc[r][0], acc[r][1], acc[r][2], acc[r][3]);
        }
        __syncthreads();
        if (ks == 0) {
            #pragma unroll
            for (int s = 0; s < 3; ++s) {
                const float* p = &s_part[(s * 96 + jg) * 16];
                #pragma unroll
                for (int r = 0; r < 4; ++r) {
                    float4 v = *(const float4*)(p + r * 4);
                    acc[r][0] += v.x; acc[r][1] += v.y; acc[r][2] += v.z; acc[r][3] += v.w;
                }
            }
            #pragma unroll
            for (int r = 0; r < 4; ++r) {
                float4 v = make_float4(acc[r][0], acc[r][1], acc[r][2], acc[r][3]);
                *(float4*)&s_gh[r * 768 + jcol] = v;
                *(float4*)&pay_out[r * 384 + jg * 4] = v;
            }
        }
        // publish own rows' x_t
        if (tid < 12) {
            int rl = tid / 6, a = tid % 6;
            pay_out[1536 + tid] = s_x[(half * 2 + rl) * 8 + a];
        }
        __threadfence();
        __syncthreads();
        if (tid == 0) {
            atomicExch(&g_flag[bid], t + 1);
            volatile int* f = &g_flag[partner];
            while (*f < t + 1) {}
            __threadfence();
        }
        __syncthreads();

        // ---- pull partner half into s_gh + partner x ----
        {
            int rr = tid / 96, off = (tid % 96) * 4;
            float4 v = __ldcg((const float4*)&pay_in[rr * 384 + off]);
            *(float4*)&s_gh[rr * 768 + (half ^ 1) * 384 + off] = v;
        }
        if (tid < 12) {
            int rl = tid / 6, a = tid % 6;
            s_x[((half ^ 1) * 2 + rl) * 8 + a] = __ldcg(&pay_in[1536 + tid]);
        }
        __syncthreads();

        // ---- gates + h update (all 4 rows, redundant across the pair) ----
        #pragma unroll
        for (int it = 0; it < 3; ++it) {
            int item = tid + it * 384;
            if (item < 1024) {
                int r = item >> 8, kk = item & 255;
                float x0 = s_x[r*8+0], x1 = s_x[r*8+1], x2 = s_x[r*8+2];
                float x3 = s_x[r*8+3], x4 = s_x[r*8+4], x5 = s_x[r*8+5];
                const float* wr = s_Wih + kk * 6;
                const float* wz = s_Wih + (256 + kk) * 6;
                const float* wn = s_Wih + (512 + kk) * 6;
                float gir = s_bih[kk]       + x0*wr[0]+x1*wr[1]+x2*wr[2]+x3*wr[3]+x4*wr[4]+x5*wr[5];
                float giz = s_bih[256 + kk] + x0*wz[0]+x1*wz[1]+x2*wz[2]+x3*wz[3]+x4*wz[4]+x5*wz[5];
                float gin = s_bih[512 + kk] + x0*wn[0]+x1*wn[1]+x2*wn[2]+x3*wn[3]+x4*wn[4]+x5*wn[5];
                float rr = sigf(gir + s_gh[r*768 + kk] + s_bhh[kk]);
                float zz = sigf(giz + s_gh[r*768 + 256 + kk] + s_bhh[256 + kk]);
                float nn = tanhfast(gin + rr * (s_gh[r*768 + 512 + kk] + s_bhh[512 + kk]));
                s_h[r*256 + kk] = (1.f - zz) * nn + zz * s_h[r*256 + kk];
            }
        }
        __syncthreads();

        // ---- out MLP for own 2 rows: 256 -> 64 -> 64 -> 6 ----
        if (tid < 256) {
            int j = tid & 63, q = tid >> 6;
            int rl = q & 1, kh2 = q >> 1;
            const float* hb = s_h + (half * 2 + rl) * 256 + kh2 * 128;
            const float* wp = s_w1 + (kh2 * 128) * 64 + j;
            float a0 = 0, a1 = 0;
            #pragma unroll 8
            for (int k = 0; k < 128; k += 2) {
                a0 += hb[k]     * wp[k * 64];
                a1 += hb[k + 1] * wp[(k + 1) * 64];
            }
            s_p1[q * 64 + j] = a0 + a1;
        }
        __syncthreads();
        if (tid < 128) {
            int rl = tid >> 6, j = tid & 63;
            s_o1[tid] = fmaxf(s_b1[j] + s_p1[rl * 64 + j] + s_p1[(rl + 2) * 64 + j], 0.f);
        }
        __syncthreads();
        if (tid < 128) {
            int rl = tid >> 6, j = tid & 63;
            float a0 = 0, a1 = 0;
            #pragma unroll 8
            for (int k = 0; k < 64; k += 2) {
                a0 += s_o1[rl*64 + k]     * s_w2[k * 64 + j];
                a1 += s_o1[rl*64 + k + 1] * s_w2[(k + 1) * 64 + j];
            }
            s_o2[tid] = fmaxf(s_b2[j] + a0 + a1, 0.f);
        }
        __syncthreads();
        if (tid < 12) {
            int rl = tid / 6, a = tid % 6;
            float d0 = 0, d1 = 0;
            #pragma unroll 8
            for (int k = 0; k < 64; k += 2) {
                d0 += s_o2[rl*64 + k]     * s_w3[k * 6 + a];
                d1 += s_o2[rl*64 + k + 1] * s_w3[(k + 1) * 6 + a];
            }
            float d = s_b3[a] + d0 + d1;
            int rloc = half * 2 + rl;
            float xn = s_x[rloc * 8 + a] + d;
            s_x[rloc * 8 + a] = xn;
            int b = b0 + rloc;
            size_t o = ((size_t)b * T + t) * 6 + a;
            out[o] = d;
            out[off2 + o] = xn;
        }
        __syncthreads();
    }
}

// ---------------------------------------------------------------------------
// launch
// ---------------------------------------------------------------------------
extern "C" void kernel_launch(void* const* d_in, const int* in_sizes, int n_in,
                              void* d_out, int out_size)
{
    int hpos = -1;
    for (int i = 0; i < n_in; ++i) if (in_sizes[i] == 1) hpos = i;

    const float* ins[23];
    int j = 0;
    for (int i = 0; i < n_in && j < 23; ++i) {
        if (i == hpos) continue;
        ins[j++] = (const float*)d_in[i];
    }
    const int* hp = (hpos >= 0) ? (const int*)d_in[hpos] : nullptr;

    // ins: 0 data | 1 enc_w1 2 enc_b1 3 enc_w2 4 enc_b2 5 enc_w3 6 enc_b3
    //      7 mlp_w1 8 mlp_b1 9 mlp_w2 10 mlp_b2 11 mlp_w3 12 mlp_b3
    //      13 W_ih 14 W_hh 15 b_ih 16 b_hh
    //      17 out_w1 18 out_b1 19 out_w2 20 out_b2 21 out_w3 22 out_b3

    const int enc_smem = ENC_SMEM_FLOATS * 4;
    const int gru_smem = GRU_SMEM_FLOATS * 4;
    cudaFuncSetAttribute(enc_kernel, cudaFuncAttributeMaxDynamicSharedMemorySize, enc_smem);
    cudaFuncSetAttribute(gru_kernel, cudaFuncAttributeMaxDynamicSharedMemorySize, gru_smem);

    zero_feat_kernel<<<512, 256>>>();
    transpose_whh_kernel<<<768, 256>>>(ins[14]);
    zero_flags_kernel<<<1, 128>>>();
    enc_kernel<<<dim3(8, 256), 256, enc_smem>>>(ins[0], ins[1], ins[2], ins[3], ins[4], ins[5], ins[6]);
    head_kernel<<<256, 512>>>(ins[7], ins[8], ins[9], ins[10], ins[11], ins[12]);
    gru_kernel<<<GRU_BLOCKS, 384, gru_smem>>>(ins[13], ins[15], ins[16],
                                              ins[17], ins[18], ins[19], ins[20], ins[21], ins[22],
                                              hp, (float*)d_out, out_size);
}

// round 7
// speedup vs baseline: 1.9529x; 1.1625x over previous
#include <cuda_runtime.h>
#include <cuda_bf16.h>
#include <cstdint>
#include <cstddef>

// ---------------------------------------------------------------------------
// Problem constants
// ---------------------------------------------------------------------------
#define BATCH   256
#define NPTS    1024
#define HID     256
#define ACT     6

// device scratch
__device__ float g_feat[BATCH * 512];
__device__ float g_gruh[BATCH * HID];
__device__ float g_WhhT[HID * 768];
__device__ unsigned g_W3tf[4 * 128 * 128];   // tf32 image, [nc][k][n]
// GRU pair-exchange payload: [parity][block][4*384 gh + 16 x] + flags
#define GRU_BLOCKS 128
__device__ float g_pay[2][GRU_BLOCKS][1552];
__device__ int   g_flag[GRU_BLOCKS];

// ---------------------------------------------------------------------------
// helpers
// ---------------------------------------------------------------------------
__device__ __forceinline__ unsigned f2tf(float x) {
    unsigned u; asm("cvt.rna.tf32.f32 %0, %1;" : "=r"(u) : "f"(x)); return u;
}

__device__ __forceinline__ void mma_tf32(float* d, const unsigned* a, const unsigned* b) {
    asm volatile(
        "mma.sync.aligned.m16n8k8.row.col.f32.tf32.tf32.f32 "
        "{%0,%1,%2,%3}, {%4,%5,%6,%7}, {%8,%9}, {%0,%1,%2,%3};\n"
        : "+f"(d[0]), "+f"(d[1]), "+f"(d[2]), "+f"(d[3])
        : "r"(a[0]), "r"(a[1]), "r"(a[2]), "r"(a[3]), "r"(b[0]), "r"(b[1]));
}

__device__ __forceinline__ float sigf(float x) { return 1.f / (1.f + __expf(-x)); }
__device__ __forceinline__ float tanhfast(float x) { return 2.f / (1.f + __expf(-2.f * x)) - 1.f; }

// ---------------------------------------------------------------------------
// prep kernels
// ---------------------------------------------------------------------------
__global__ void zero_feat_kernel() {
    g_feat[blockIdx.x * 256 + threadIdx.x] = 0.f;
}

__global__ void transpose_whh_kernel(const float* __restrict__ Whh) {
    int idx = blockIdx.x * 256 + threadIdx.x;
    int k = idx / 768, j = idx - k * 768;
    g_WhhT[idx] = Whh[j * 256 + k];
}

__global__ void zero_flags_kernel() {
    if (threadIdx.x < GRU_BLOCKS) g_flag[threadIdx.x] = 0;
}

// W3 [128k][512n] -> tf32 image [nc][k][n(128)]
__global__ void prep_w3_kernel(const float* __restrict__ w3) {
    int idx = blockIdx.x * 256 + threadIdx.x;   // 65536
    int nc = idx >> 14, r = idx & 16383;
    int k = r >> 7, n = r & 127;
    g_W3tf[idx] = f2tf(w3[(size_t)k * 512 + nc * 128 + n]);
}

// ---------------------------------------------------------------------------
// Fused PointNet encoder: 3->64->128 (fp32 SIMT) -> 512 (tf32 mma)
// grid (8 chunks, 256 batches), 512 threads (16 warps), 128 points/block
// ---------------------------------------------------------------------------
#define ENC_HP_LD 132
#define ENC_SW_LD 136
#define ENC_SMEM_FLOATS (16896 + 17920)

__global__ void __launch_bounds__(512) enc_kernel(
    const float* __restrict__ data,
    const float* __restrict__ w1, const float* __restrict__ b1,
    const float* __restrict__ w2, const float* __restrict__ b2,
    const float* __restrict__ b3)
{
    extern __shared__ float sm[];
    float* Hp   = sm;                 // [128 pts][128 k] tf32 bits, LD=132
    float* work = sm + 16896;
    float* rA   = work;               // layer1/2: H64T + W2
    float* sW   = work;               // layer3: W3 chunk [128][136] tf32
    float* sRed = work + 17408;       // 4x128
    __shared__ float sPts[128 * 3];

    const int tid   = threadIdx.x;
    const int b     = blockIdx.y;
    const int chunk = blockIdx.x;

    // ---- stage points + W2 ----
    const float* dptr = data + (size_t)(b * NPTS + chunk * 128) * 3;
    if (tid < 384) sPts[tid] = dptr[tid];
    for (int i = tid * 4; i < 8192; i += 2048)
        *(float4*)(rA + 8192 + i) = *(const float4*)(w2 + i);
    __syncthreads();

    // ---- layer 1: H64T[k][i] ----
    #pragma unroll
    for (int it = 0; it < 16; ++it) {
        int idx = tid + it * 512;
        int k = idx >> 7, i = idx & 127;
        float v = b1[k] + sPts[i*3] * w1[k] + sPts[i*3+1] * w1[64 + k] + sPts[i*3+2] * w1[128 + k];
        rA[idx] = fmaxf(v, 0.f);
    }
    __syncthreads();

    // ---- layer 2: 8x4 per thread -> Hp tf32 ----
    {
        const int i0 = (tid >> 5) * 8;      // 16 groups x 8 rows
        const int j0 = (tid & 31) * 4;      // 32 groups x 4 cols
        float acc[8][4];
        #pragma unroll
        for (int a = 0; a < 8; ++a)
            #pragma unroll
            for (int c = 0; c < 4; ++c) acc[a][c] = 0.f;

        #pragma unroll 4
        for (int k = 0; k < 64; ++k) {
            float av[8], wv[4];
            *(float4*)&av[0] = *(float4*)(rA + k*128 + i0);
            *(float4*)&av[4] = *(float4*)(rA + k*128 + i0 + 4);
            *(float4*)&wv[0] = *(float4*)(rA + 8192 + k*128 + j0);
            #pragma unroll
            for (int a = 0; a < 8; ++a)
                #pragma unroll
                for (int c = 0; c < 4; ++c) acc[a][c] += av[a] * wv[c];
        }
        float bj[4];
        #pragma unroll
        for (int c = 0; c < 4; ++c) bj[c] = b2[j0 + c];
        unsigned* Hpu = (unsigned*)Hp;
        #pragma unroll
        for (int a = 0; a < 8; ++a) {
            unsigned uv[4];
            #pragma unroll
            for (int c = 0; c < 4; ++c)
                uv[c] = f2tf(fmaxf(acc[a][c] + bj[c], 0.f));
            *(uint4*)(Hpu + (i0 + a) * ENC_HP_LD + j0) = make_uint4(uv[0], uv[1], uv[2], uv[3]);
        }
    }
    __syncthreads();

    // ---- layer 3: tf32 mma, warp grid 4x4 (M32 x N32 per warp) ----
    const int lane = tid & 31, wrp = tid >> 5;
    const int wm = wrp & 3, wn = wrp >> 2;
    const int qp = lane >> 2, rr = lane & 3;
    const unsigned* Hpu = (const unsigned*)Hp;
    unsigned* sWu = (unsigned*)sW;

    for (int nc = 0; nc < 4; ++nc) {
        // stage W3 chunk: pure float4 copies of pre-converted image
        {
            const float* src = (const float*)(g_W3tf + nc * 16384);
            for (int i = tid * 4; i < 16384; i += 2048) {
                int k = i >> 7, n = i & 127;
                *(float4*)(sW + k * ENC_SW_LD + n) = *(const float4*)(src + i);
            }
        }
        __syncthreads();

        float acc[2][4][4];
        #pragma unroll
        for (int mt = 0; mt < 2; ++mt)
            #pragma unroll
            for (int nt = 0; nt < 4; ++nt)
                #pragma unroll
                for (int q = 0; q < 4; ++q) acc[mt][nt][q] = 0.f;

        #pragma unroll 1
        for (int ks = 0; ks < 16; ++ks) {
            int k0 = ks * 8;
            unsigned af[2][4];
            #pragma unroll
            for (int mt = 0; mt < 2; ++mt) {
                int r0 = wm * 32 + mt * 16 + qp;
                af[mt][0] = Hpu[r0 * ENC_HP_LD + k0 + rr];
                af[mt][1] = Hpu[(r0 + 8) * ENC_HP_LD + k0 + rr];
                af[mt][2] = Hpu[r0 * ENC_HP_LD + k0 + rr + 4];
                af[mt][3] = Hpu[(r0 + 8) * ENC_HP_LD + k0 + rr + 4];
            }
            unsigned bf[4][2];
            #pragma unroll
            for (int nt = 0; nt < 4; ++nt) {
                int n = wn * 32 + nt * 8 + qp;
                bf[nt][0] = sWu[(k0 + rr) * ENC_SW_LD + n];
                bf[nt][1] = sWu[(k0 + 4 + rr) * ENC_SW_LD + n];
            }
            #pragma unroll
            for (int mt = 0; mt < 2; ++mt)
                #pragma unroll
                for (int nt = 0; nt < 4; ++nt)
                    mma_tf32(acc[mt][nt], af[mt], bf[nt]);
        }

        // epilogue: bias + relu + col-max over warp's 32 rows, cross-warp via sRed
        #pragma unroll
        for (int nt = 0; nt < 4; ++nt) {
            int n = wn * 32 + nt * 8 + 2 * rr;
            float bv0 = b3[nc * 128 + n];
            float bv1 = b3[nc * 128 + n + 1];
            float m0 = 0.f, m1 = 0.f;
            #pragma unroll
            for (int mt = 0; mt < 2; ++mt) {
                float* d = acc[mt][nt];
                m0 = fmaxf(m0, fmaxf(d[0] + bv0, d[2] + bv0));
                m1 = fmaxf(m1, fmaxf(d[1] + bv1, d[3] + bv1));
            }
            #pragma unroll
            for (int s = 4; s < 32; s <<= 1) {
                m0 = fmaxf(m0, __shfl_xor_sync(0xffffffffu, m0, s));
                m1 = fmaxf(m1, __shfl_xor_sync(0xffffffffu, m1, s));
            }
            if (qp == 0) {
                sRed[wm * 128 + n]     = m0;
                sRed[wm * 128 + n + 1] = m1;
            }
        }
        __syncthreads();
        if (tid < 128) {
            float m = fmaxf(fmaxf(sRed[tid], sRed[128 + tid]),
                            fmaxf(sRed[256 + tid], sRed[384 + tid]));
            atomicMax((int*)&g_feat[b * 512 + nc * 128 + tid], __float_as_int(m));
        }
        __syncthreads();
    }
}

// ---------------------------------------------------------------------------
// Head MLP: 512 -> 256 -> 128 -> 256, 512 threads, k-split + smem combine
// ---------------------------------------------------------------------------
__global__ void __launch_bounds__(512) head_kernel(
    const float* __restrict__ w1, const float* __restrict__ b1,
    const float* __restrict__ w2, const float* __restrict__ b2,
    const float* __restrict__ w3, const float* __restrict__ b3)
{
    __shared__ float sh[512];
    __shared__ float pp[512];
    __shared__ float s1[256];
    __shared__ float s2[128];
    int b = blockIdx.x, tid = threadIdx.x;
    sh[tid] = g_feat[b * 512 + tid];
    __syncthreads();
    {
        int j = tid & 255, half = tid >> 8, k0 = half * 256;
        const float* wp = w1 + (size_t)k0 * 256 + j;
        float a0 = 0, a1 = 0, a2 = 0, a3 = 0;
        #pragma unroll 8
        for (int k = 0; k < 256; k += 4) {
            a0 += sh[k0 + k]     * wp[(size_t)k * 256];
            a1 += sh[k0 + k + 1] * wp[(size_t)(k + 1) * 256];
            a2 += sh[k0 + k + 2] * wp[(size_t)(k + 2) * 256];
            a3 += sh[k0 + k + 3] * wp[(size_t)(k + 3) * 256];
        }
        pp[tid] = (a0 + a1) + (a2 + a3);
    }
    __syncthreads();
    if (tid < 256) s1[tid] = fmaxf(b1[tid] + pp[tid] + pp[tid + 256], 0.f);
    __syncthreads();
    {
        int j = tid & 127, q = tid >> 7, k0 = q * 64;
        const float* wp = w2 + k0 * 128 + j;
        float a0 = 0, a1 = 0;
        #pragma unroll 8
        for (int k = 0; k < 64; k += 2) {
            a0 += s1[k0 + k]     * wp[k * 128];
            a1 += s1[k0 + k + 1] * wp[(k + 1) * 128];
        }
        pp[tid] = a0 + a1;
    }
    __syncthreads();
    if (tid < 128) s2[tid] = fmaxf(b2[tid] + pp[tid] + pp[tid + 128] + pp[tid + 256] + pp[tid + 384], 0.f);
    __syncthreads();
    {
        int j = tid & 255, half = tid >> 8, k0 = half * 64;
        const float* wp = w3 + k0 * 256 + j;
        float a0 = 0, a1 = 0;
        #pragma unroll 8
        for (int k = 0; k < 64; k += 2) {
            a0 += s2[k0 + k]     * wp[k * 256];
            a1 += s2[k0 + k + 1] * wp[(k + 1) * 256];
        }
        pp[tid] = a0 + a1;
    }
    __syncthreads();
    if (tid < 256) g_gruh[b * HID + tid] = b3[tid] + pp[tid] + pp[tid + 256];
}

// ---------------------------------------------------------------------------
// GRU rollout v3: 128 blocks = 64 pairs; each pair shares 4 batch rows and
// splits the gh GEMM j-dim in half; halves exchange via L2 payload + flag.
// (identical to R6 passing version)
// ---------------------------------------------------------------------------
#define GRU_SMEM_FLOATS 36392

__global__ void __launch_bounds__(384) gru_kernel(
    const float* __restrict__ Wih, const float* __restrict__ bih, const float* __restrict__ bhh,
    const float* __restrict__ ow1, const float* __restrict__ ob1,
    const float* __restrict__ ow2, const float* __restrict__ ob2,
    const float* __restrict__ ow3, const float* __restrict__ ob3,
    const int* __restrict__ horizon_p, float* __restrict__ out, int out_size)
{
    extern __shared__ float sm[];
    float* s_Wih  = sm;
    float* s_bih  = s_Wih + 4608;
    float* s_bhh  = s_bih + 768;
    float* s_w1   = s_bhh + 768;
    float* s_w2   = s_w1 + 16384;
    float* s_w3   = s_w2 + 4096;
    float* s_b1   = s_w3 + 384;
    float* s_b2   = s_b1 + 64;
    float* s_b3   = s_b2 + 64;
    float* s_h    = s_b3 + 8;
    float* s_x    = s_h + 1024;
    float* s_gh   = s_x + 32;
    float* s_part = s_gh + 3072;
    float* s_p1   = s_part + 4608;
    float* s_o1   = s_p1 + 256;
    float* s_o2   = s_o1 + 128;

    const int tid     = threadIdx.x;
    const int bid     = blockIdx.x;
    const int pairid  = bid >> 1;
    const int half    = bid & 1;
    const int partner = bid ^ 1;
    const int b0      = pairid * 4;

    for (int i = tid; i < 4608;  i += 384) s_Wih[i] = Wih[i];
    for (int i = tid; i < 768;   i += 384) { s_bih[i] = bih[i]; s_bhh[i] = bhh[i]; }
    for (int i = tid; i < 16384; i += 384) s_w1[i] = ow1[i];
    for (int i = tid; i < 4096;  i += 384) s_w2[i] = ow2[i];
    if (tid < 384) s_w3[tid] = ow3[tid];
    if (tid < 64) { s_b1[tid] = ob1[tid]; s_b2[tid] = ob2[tid]; }
    if (tid < 6)  s_b3[tid] = ob3[tid];
    for (int i = tid; i < 1024; i += 384) {
        int r = i >> 8, k = i & 255;
        s_h[i] = g_gruh[(b0 + r) * HID + k];
    }
    if (tid < 32) s_x[tid] = 0.f;
    __syncthreads();

    int T = 50;
    if (horizon_p) {
        int v = *horizon_p;
        if (v > 0 && v <= 1000000) T = v;
        else {
            float fv = __int_as_float(v);
            if (fv > 0.f && fv <= 1000000.f) T = (int)fv;
        }
    }
    const int off2 = out_size >> 1;

    const int jg   = tid % 96;
    const int ks   = tid / 96;
    const int k0   = ks * 64;
    const int jcol = half * 384 + jg * 4;
    const float* Wcol = g_WhhT + jcol;

    for (int t = 0; t < T; ++t) {
        const int par = t & 1;
        float* pay_out = &g_pay[par][bid][0];
        const float* pay_in = &g_pay[par][partner][0];

        float acc[4][4];
        #pragma unroll
        for (int r = 0; r < 4; ++r)
            #pragma unroll
            for (int c = 0; c < 4; ++c) acc[r][c] = 0.f;

        #pragma unroll 2
        for (int kk = 0; kk < 64; kk += 4) {
            float4 h0 = *(float4*)&s_h[0 * 256 + k0 + kk];
            float4 h1 = *(float4*)&s_h[1 * 256 + k0 + kk];
            float4 h2 = *(float4*)&s_h[2 * 256 + k0 + kk];
            float4 h3 = *(float4*)&s_h[3 * 256 + k0 + kk];
            const float* wb = Wcol + (size_t)(k0 + kk) * 768;
            #pragma unroll
            for (int q = 0; q < 4; ++q) {
                float4 w = *(const float4*)(wb + (size_t)q * 768);
                float a0 = (q == 0) ? h0.x : (q == 1) ? h0.y : (q == 2) ? h0.z : h0.w;
                float a1 = (q == 0) ? h1.x : (q == 1) ? h1.y : (q == 2) ? h1.z : h1.w;
                float a2 = (q == 0) ? h2.x : (q == 1) ? h2.y : (q == 2) ? h2.z : h2.w;
                float a3 = (q == 0) ? h3.x : (q == 1) ? h3.y : (q == 2) ? h3.z : h3.w;
                acc[0][0] += a0*w.x; acc[0][1] += a0*w.y; acc[0][2] += a0*w.z; acc[0][3] += a0*w.w;
                acc[1][0] += a1*w.x; acc[1][1] += a1*w.y; acc[1][2] += a1*w.z; acc[1][3] += a1*w.w;
                acc[2][0] += a2*w.x; acc[2][1] += a2*w.y; acc[2][2] += a2*w.z; acc[2][3] += a2*w.w;
                acc[3][0] += a3*w.x; acc[3][1] += a3*w.y; acc[3][2] += a3*w.z; acc[3][3] += a3*w.w;
            }
        }

        if (ks > 0) {
            float* p = &s_part[((ks - 1) * 96 + jg) * 16];
            #pragma unroll
            for (int r = 0; r < 4; ++r)
                *(float4*)(p + r * 4) = make_float4(acc[r][0], acc[r][1], acc[r][2], acc[r][3]);
        }
        __syncthreads();
        if (ks == 0) {
            #pragma unroll
            for (int s = 0; s < 3; ++s) {
                const float* p = &s_part[(s * 96 + jg) * 16];
                #pragma unroll
                for (int r = 0; r < 4; ++r) {
                    float4 v = *(const float4*)(p + r * 4);
                    acc[r][0] += v.x; acc[r][1] += v.y; acc[r][2] += v.z; acc[r][3] += v.w;
                }
            }
            #pragma unroll
            for (int r = 0; r < 4; ++r) {
                float4 v = make_float4(acc[r][0], acc[r][1], acc[r][2], acc[r][3]);
                *(float4*)&s_gh[r * 768 + jcol] = v;
                *(float4*)&pay_out[r * 384 + jg * 4] = v;
            }
        }
        if (tid < 12) {
            int rl = tid / 6, a = tid % 6;
            pay_out[1536 + tid] = s_x[(half * 2 + rl) * 8 + a];
        }
        __threadfence();
        __syncthreads();
        if (tid == 0) {
            atomicExch(&g_flag[bid], t + 1);
            volatile int* f = &g_flag[partner];
            while (*f < t + 1) {}
            __threadfence();
        }
        __syncthreads();

        {
            int rr = tid / 96, off = (tid % 96) * 4;
            float4 v = __ldcg((const float4*)&pay_in[rr * 384 + off]);
            *(float4*)&s_gh[rr * 768 + (half ^ 1) * 384 + off] = v;
        }
        if (tid < 12) {
            int rl = tid / 6, a = tid % 6;
            s_x[((half ^ 1) * 2 + rl) * 8 + a] = __ldcg(&pay_in[1536 + tid]);
        }
        __syncthreads();

        #pragma unroll
        for (int it = 0; it < 3; ++it) {
            int item = tid + it * 384;
            if (item < 1024) {
                int r = item >> 8, kk = item & 255;
                float x0 = s_x[r*8+0], x1 = s_x[r*8+1], x2 = s_x[r*8+2];
                float x3 = s_x[r*8+3], x4 = s_x[r*8+4], x5 = s_x[r*8+5];
                const float* wr = s_Wih + kk * 6;
                const float* wz = s_Wih + (256 + kk) * 6;
                const float* wn = s_Wih + (512 + kk) * 6;
                float gir = s_bih[kk]       + x0*wr[0]+x1*wr[1]+x2*wr[2]+x3*wr[3]+x4*wr[4]+x5*wr[5];
                float giz = s_bih[256 + kk] + x0*wz[0]+x1*wz[1]+x2*wz[2]+x3*wz[3]+x4*wz[4]+x5*wz[5];
                float gin = s_bih[512 + kk] + x0*wn[0]+x1*wn[1]+x2*wn[2]+x3*wn[3]+x4*wn[4]+x5*wn[5];
                float rr = sigf(gir + s_gh[r*768 + kk] + s_bhh[kk]);
                float zz = sigf(giz + s_gh[r*768 + 256 + kk] + s_bhh[256 + kk]);
                float nn = tanhfast(gin + rr * (s_gh[r*768 + 512 + kk] + s_bhh[512 + kk]));
                s_h[r*256 + kk] = (1.f - zz) * nn + zz * s_h[r*256 + kk];
            }
        }
        __syncthreads();

        if (tid < 256) {
            int j = tid & 63, q = tid >> 6;
            int rl = q & 1, kh2 = q >> 1;
            const float* hb = s_h + (half * 2 + rl) * 256 + kh2 * 128;
            const float* wp = s_w1 + (kh2 * 128) * 64 + j;
            float a0 = 0, a1 = 0;
            #pragma unroll 8
            for (int k = 0; k < 128; k += 2) {
                a0 += hb[k]     * wp[k * 64];
                a1 += hb[k + 1] * wp[(k + 1) * 64];
            }
            s_p1[q * 64 + j] = a0 + a1;
        }
        __syncthreads();
        if (tid < 128) {
            int rl = tid >> 6, j = tid & 63;
            s_o1[tid] = fmaxf(s_b1[j] + s_p1[rl * 64 + j] + s_p1[(rl + 2) * 64 + j], 0.f);
        }
        __syncthreads();
        if (tid < 128) {
            int rl = tid >> 6, j = tid & 63;
            float a0 = 0, a1 = 0;
            #pragma unroll 8
            for (int k = 0; k < 64; k += 2) {
                a0 += s_o1[rl*64 + k]     * s_w2[k * 64 + j];
                a1 += s_o1[rl*64 + k + 1] * s_w2[(k + 1) * 64 + j];
            }
            s_o2[tid] = fmaxf(s_b2[j] + a0 + a1, 0.f);
        }
        __syncthreads();
        if (tid < 12) {
            int rl = tid / 6, a = tid % 6;
            float d0 = 0, d1 = 0;
            #pragma unroll 8
            for (int k = 0; k < 64; k += 2) {
                d0 += s_o2[rl*64 + k]     * s_w3[k * 6 + a];
                d1 += s_o2[rl*64 + k + 1] * s_w3[(k + 1) * 6 + a];
            }
            float d = s_b3[a] + d0 + d1;
            int rloc = half * 2 + rl;
            float xn = s_x[rloc * 8 + a] + d;
            s_x[rloc * 8 + a] = xn;
            int b = b0 + rloc;
            size_t o = ((size_t)b * T + t) * 6 + a;
            out[o] = d;
            out[off2 + o] = xn;
        }
        __syncthreads();
    }
}

// ---------------------------------------------------------------------------
// launch
// ---------------------------------------------------------------------------
extern "C" void kernel_launch(void* const* d_in, const int* in_sizes, int n_in,
                              void* d_out, int out_size)
{
    int hpos = -1;
    for (int i = 0; i < n_in; ++i) if (in_sizes[i] == 1) hpos = i;

    const float* ins[23];
    int j = 0;
    for (int i = 0; i < n_in && j < 23; ++i) {
        if (i == hpos) continue;
        ins[j++] = (const float*)d_in[i];
    }
    const int* hp = (hpos >= 0) ? (const int*)d_in[hpos] : nullptr;

    // ins: 0 data | 1 enc_w1 2 enc_b1 3 enc_w2 4 enc_b2 5 enc_w3 6 enc_b3
    //      7 mlp_w1 8 mlp_b1 9 mlp_w2 10 mlp_b2 11 mlp_w3 12 mlp_b3
    //      13 W_ih 14 W_hh 15 b_ih 16 b_hh
    //      17 out_w1 18 out_b1 19 out_w2 20 out_b2 21 out_w3 22 out_b3

    const int enc_smem = ENC_SMEM_FLOATS * 4;
    const int gru_smem = GRU_SMEM_FLOATS * 4;
    cudaFuncSetAttribute(enc_kernel, cudaFuncAttributeMaxDynamicSharedMemorySize, enc_smem);
    cudaFuncSetAttribute(gru_kernel, cudaFuncAttributeMaxDynamicSharedMemorySize, gru_smem);

    zero_feat_kernel<<<512, 256>>>();
    transpose_whh_kernel<<<768, 256>>>(ins[14]);
    prep_w3_kernel<<<256, 256>>>(ins[5]);
    zero_flags_kernel<<<1, 128>>>();
    enc_kernel<<<dim3(8, 256), 512, enc_smem>>>(ins[0], ins[1], ins[2], ins[3], ins[4], ins[6]);
    head_kernel<<<256, 512>>>(ins[7], ins[8], ins[9], ins[10], ins[11], ins[12]);
    gru_kernel<<<GRU_BLOCKS, 384, gru_smem>>>(ins[13], ins[15], ins[16],
                                              ins[17], ins[18], ins[19], ins[20], ins[21], ins[22],
                                              hp, (float*)d_out, out_size);
}